// round 14
// baseline (speedup 1.0000x reference)
#include <cuda_runtime.h>
#include <cuda.h>
#include <cuda_fp16.h>
#include <cstdint>

// ---------------- problem constants ----------------
#define NNODES 16384
#define DIM    128
#define KC     32                          // K per chunk
#define CHUNKS (NNODES / KC)               // 512
#define KSPLIT 4
#define SEG_CHUNKS (CHUNKS / KSPLIT)       // 128 chunks per CTA
#define STAGES 3
#define MTILE  128
#define NMTILES (NNODES / MTILE)           // 128
#define PREP_CTAS 256                      // prep role CTAs (64 nodes each)
#define GEMM_CTAS (NMTILES * KSPLIT)       // 512

// B (zh) padded chunk layout: [chunk][o:128][40 halves] (32 data + 8 pad, 80B rows)
#define BROW_H   40
#define BROW_B   80
#define BCHUNK_H (DIM * BROW_H)            // 5120 halves = 10240 B
#define BCHUNK_B (BCHUNK_H * 2)

#define A32_BYTES (MTILE * KC * 4)         // 16384 B per stage (SW128 swizzled fp32)
#define A16_ROWB  80                       // padded fp16 A row stride
#define A16_BYTES (MTILE * A16_ROWB)       // 10240 B per ping buffer
#define TXB (A32_BYTES + BCHUNK_B)         // 26624

// gemm smem layout (inside the shared dynamic region; no static __shared__
// anywhere — a static alloc shifts the dynamic base and breaks TMA's 128B
// alignment: root cause of the R10/R12 crashes)
#define SM_MBAR 0
#define SM_A32  1024
#define SM_B    (1024 + STAGES * A32_BYTES)              // 50176
#define SM_A16  (SM_B + STAGES * BCHUNK_B)               // 80896
#define GEMM_SMEM_USED (SM_A16 + 2 * A16_BYTES)          // 101376

// prep smem layout
#define PT_ROWB 272
#define PT_XH   1024
#define PT_WH   (PT_XH + 64 * PT_ROWB)     // 18432
#define PT_ZS   (PT_WH + 256 * PT_ROWB)    // 88064
#define ZS_STRH 72
#define PREP_SMEM_USED (PT_ZS + 128 * ZS_STRH * 2)       // 106496

#define FUSED_SMEM 106496                  // max(gemm, prep) -> 2 CTAs/SM

// scratch (__device__ globals; 256B-aligned)
__device__ __align__(256) __half g_zh[CHUNKS * BCHUNK_H];       // 5 MB
__device__ __align__(256) float  g_u [NNODES * DIM];            // 8 MB
__device__ __align__(256) float  g_part[KSPLIT * NNODES * DIM]; // 32 MB
__device__ __align__(256) int    g_flag[PREP_CTAS];             // zero-init; cleared by combine

// ---------------- PTX helpers (compute_103-baseline only) ----------------
__device__ __forceinline__ uint32_t smem_u32(const void* p) {
    uint32_t a;
    asm("{ .reg .u64 t; cvta.to.shared.u64 t, %1; cvt.u32.u64 %0, t; }" : "=r"(a) : "l"(p));
    return a;
}
__device__ __forceinline__ void mbar_init(uint32_t mbar, uint32_t cnt) {
    asm volatile("mbarrier.init.shared.b64 [%0], %1;" :: "r"(mbar), "r"(cnt) : "memory");
}
__device__ __forceinline__ void mbar_expect_tx(uint32_t mbar, uint32_t bytes) {
    asm volatile("mbarrier.arrive.expect_tx.shared.b64 _, [%0], %1;" :: "r"(mbar), "r"(bytes) : "memory");
}
__device__ __forceinline__ void mbar_wait(uint32_t mbar, uint32_t parity) {
    asm volatile(
        "{\n\t.reg .pred P;\n\t"
        "W_%=:\n\t"
        "mbarrier.try_wait.parity.shared.b64 P, [%0], %1, 0x989680;\n\t"
        "@P bra D_%=;\n\t"
        "bra W_%=;\n\t"
        "D_%=:\n\t}"
        :: "r"(mbar), "r"(parity) : "memory");
}
__device__ __forceinline__ void tma_2d(uint32_t dst, const CUtensorMap* map,
                                       int cx, int cy, uint32_t mbar) {
    asm volatile(
        "cp.async.bulk.tensor.2d.shared::cta.global.tile.mbarrier::complete_tx::bytes "
        "[%0], [%1, {%2, %3}], [%4];"
        :: "r"(dst), "l"(map), "r"(cx), "r"(cy), "r"(mbar) : "memory");
}
__device__ __forceinline__ void bulk_cp(uint32_t dst, const void* src, uint32_t bytes, uint32_t mbar) {
    asm volatile(
        "cp.async.bulk.shared::cta.global.mbarrier::complete_tx::bytes [%0], [%1], %2, [%3];"
        :: "r"(dst), "l"(src), "r"(bytes), "r"(mbar) : "memory");
}
__device__ __forceinline__ void ldm_x4(uint32_t* r, uint32_t addr) {
    asm volatile("ldmatrix.sync.aligned.m8n8.x4.shared.b16 {%0,%1,%2,%3}, [%4];"
        : "=r"(r[0]), "=r"(r[1]), "=r"(r[2]), "=r"(r[3]) : "r"(addr));
}
__device__ __forceinline__ void mma16816(float* c, const uint32_t* a, const uint32_t* b) {
    asm volatile("mma.sync.aligned.m16n8k16.row.col.f32.f16.f16.f32 "
        "{%0,%1,%2,%3}, {%4,%5,%6,%7}, {%8,%9}, {%0,%1,%2,%3};"
        : "+f"(c[0]), "+f"(c[1]), "+f"(c[2]), "+f"(c[3])
        : "r"(a[0]), "r"(a[1]), "r"(a[2]), "r"(a[3]), "r"(b[0]), "r"(b[1]));
}
// acquire-poll on a producer flag (tid0 only)
__device__ __forceinline__ void wait_flag(const int* p) {
    int v;
    do {
        asm volatile("ld.acquire.gpu.b32 %0, [%1];" : "=r"(v) : "l"(p));
    } while (v == 0);
}

// fp32 SW128 stage (128 rows x 128B) -> padded fp16 ping buffer (256 threads)
__device__ __forceinline__ void convert_chunk(const char* a32, char* a16, int tid) {
    const int crow = tid >> 1, chalf = tid & 1;
    const uint32_t rsw = (uint32_t)(crow & 7) << 4;
    char* dst = a16 + crow * A16_ROWB + chalf * 32;
    #pragma unroll
    for (int jp = 0; jp < 2; ++jp) {
        uint32_t b0 = (uint32_t)(crow * 128 + chalf * 64 + jp * 32);
        float4 v0 = *reinterpret_cast<const float4*>(a32 + (b0 ^ rsw));
        float4 v1 = *reinterpret_cast<const float4*>(a32 + ((b0 + 16) ^ rsw));
        __half2 h0 = __floats2half2_rn(v0.x, v0.y);
        __half2 h1 = __floats2half2_rn(v0.z, v0.w);
        __half2 h2 = __floats2half2_rn(v1.x, v1.y);
        __half2 h3 = __floats2half2_rn(v1.z, v1.w);
        uint4 pk;
        pk.x = *reinterpret_cast<uint32_t*>(&h0);
        pk.y = *reinterpret_cast<uint32_t*>(&h1);
        pk.z = *reinterpret_cast<uint32_t*>(&h2);
        pk.w = *reinterpret_cast<uint32_t*>(&h3);
        *reinterpret_cast<uint4*>(dst + jp * 16) = pk;
    }
}

// ============================================================================
// Prep role (CTAs 0..255): 64 nodes/CTA, tensor-core x@W^T.
//   z -> fp16 g_zh (padded chunk layout) ; u -> fp32 g_u ; then sets its
//   ready flag (release) covering chunks 2*bx, 2*bx+1.
// ============================================================================
__device__ void prep_body(char* smem, uint32_t sb, int bx,
                          const float* __restrict__ x,
                          const float* __restrict__ W,
                          const float* __restrict__ b) {
    const int tid  = threadIdx.x;
    const int lane = tid & 31;
    const int w    = tid >> 5;
    const int node0 = bx * 64;

    #pragma unroll
    for (int i = 0; i < 8; ++i) {
        int idx = tid + i * 256;
        int row = idx >> 5, c4 = idx & 31;
        float4 v = reinterpret_cast<const float4*>(x + (size_t)(node0 + row) * DIM)[c4];
        __half2 h0 = __floats2half2_rn(v.x, v.y);
        __half2 h1 = __floats2half2_rn(v.z, v.w);
        uint2 pk;
        pk.x = *reinterpret_cast<uint32_t*>(&h0);
        pk.y = *reinterpret_cast<uint32_t*>(&h1);
        *reinterpret_cast<uint2*>(smem + PT_XH + row * PT_ROWB + c4 * 8) = pk;
    }
    #pragma unroll
    for (int i = 0; i < 32; ++i) {
        int idx = tid + i * 256;
        int j = idx >> 5, c4 = idx & 31;
        const float* src = (j < DIM) ? (W + j * 256 + DIM) : (W + (j - DIM) * 256);
        float4 v = reinterpret_cast<const float4*>(src)[c4];
        __half2 h0 = __floats2half2_rn(v.x, v.y);
        __half2 h1 = __floats2half2_rn(v.z, v.w);
        uint2 pk;
        pk.x = *reinterpret_cast<uint32_t*>(&h0);
        pk.y = *reinterpret_cast<uint32_t*>(&h1);
        *reinterpret_cast<uint2*>(smem + PT_WH + j * PT_ROWB + c4 * 8) = pk;
    }
    __syncthreads();

    const int m0w = (w >> 2) * 32;
    const int n0w = (w & 3) * 64;
    uint32_t aoff[2];
    #pragma unroll
    for (int mi = 0; mi < 2; ++mi)
        aoff[mi] = (uint32_t)(PT_XH + (m0w + mi * 16 + (lane & 15)) * PT_ROWB + (lane >> 4) * 16);
    const int bg = lane >> 3;
    const uint32_t boff =
        (uint32_t)(PT_WH + (n0w + ((bg >> 1) & 1) * 8 + (lane & 7)) * PT_ROWB + (bg & 1) * 16);

    float acc[2][8][4];
    #pragma unroll
    for (int i = 0; i < 2; i++)
        #pragma unroll
        for (int j = 0; j < 8; j++)
            #pragma unroll
            for (int k = 0; k < 4; k++) acc[i][j][k] = 0.f;

    #pragma unroll
    for (int ks = 0; ks < 8; ++ks) {
        uint32_t afr[2][4];
        #pragma unroll
        for (int mi = 0; mi < 2; ++mi)
            ldm_x4(afr[mi], sb + aoff[mi] + ks * 32);
        uint32_t bfr[4][4];
        #pragma unroll
        for (int nt2 = 0; nt2 < 4; ++nt2)
            ldm_x4(bfr[nt2], sb + boff + nt2 * 16 * PT_ROWB + ks * 32);
        #pragma unroll
        for (int mi = 0; mi < 2; ++mi)
            #pragma unroll
            for (int nt = 0; nt < 8; ++nt)
                mma16816(acc[mi][nt], afr[mi], &bfr[nt >> 1][(nt & 1) * 2]);
    }

    __half* zs = reinterpret_cast<__half*>(smem + PT_ZS);
    if (n0w < 128) {
        #pragma unroll
        for (int mi = 0; mi < 2; ++mi) {
            int r = m0w + mi * 16 + (lane >> 2);
            #pragma unroll
            for (int nt = 0; nt < 8; ++nt) {
                int n = n0w + nt * 8 + 2 * (lane & 3);
                const float* a = acc[mi][nt];
                zs[n * ZS_STRH + r]           = __float2half_rn(a[0]);
                zs[(n + 1) * ZS_STRH + r]     = __float2half_rn(a[1]);
                zs[n * ZS_STRH + r + 8]       = __float2half_rn(a[2]);
                zs[(n + 1) * ZS_STRH + r + 8] = __float2half_rn(a[3]);
            }
        }
    } else {
        #pragma unroll
        for (int mi = 0; mi < 2; ++mi) {
            int r = m0w + mi * 16 + (lane >> 2);
            #pragma unroll
            for (int nt = 0; nt < 8; ++nt) {
                int o = n0w - 128 + nt * 8 + 2 * (lane & 3);
                float2 bo = *reinterpret_cast<const float2*>(b + o);
                const float* a = acc[mi][nt];
                *reinterpret_cast<float2*>(g_u + (size_t)(node0 + r) * DIM + o) =
                    make_float2(a[0] + bo.x, a[1] + bo.y);
                *reinterpret_cast<float2*>(g_u + (size_t)(node0 + r + 8) * DIM + o) =
                    make_float2(a[2] + bo.x, a[3] + bo.y);
            }
        }
    }
    __syncthreads();

    {
        int o = tid >> 1, q = tid & 1;
        const uint4* src = reinterpret_cast<const uint4*>(smem + PT_ZS + o * (ZS_STRH * 2) + q * 64);
        uint4* dst = reinterpret_cast<uint4*>(g_zh + (size_t)(bx * 2 + q) * BCHUNK_H + o * BROW_H);
        #pragma unroll
        for (int i = 0; i < 4; i++) dst[i] = src[i];
    }

    // publish: chunks 2*bx, 2*bx+1 ready
    __threadfence();
    __syncthreads();
    if (tid == 0) atomicExch(&g_flag[bx], 1);
}

// ============================================================================
// Gemm role (CTAs 256..767): MTILE=128, split-K x4, proven R9 structure.
//   B bulk_cp gated on prep ready flags (tid0 acquire-poll).
// ============================================================================
__device__ void gemm_body(char* smem, uint32_t sb, int gbx,
                          const CUtensorMap* tma_a) {
    const uint32_t MB = sb + SM_MBAR;
    const int tid  = threadIdx.x;
    const int lane = tid & 31;
    const int w    = tid >> 5;
    const int seg  = gbx & (KSPLIT - 1);
    const int mt   = gbx >> 2;
    const int m0g  = mt * MTILE;
    const int c0   = seg * SEG_CHUNKS;
    const int m0w  = (w >> 2) * 64;     // warp tile 64x32
    const int n0w  = (w & 3) * 32;

    if (tid == 0) {
        #pragma unroll
        for (int s = 0; s < STAGES; ++s) mbar_init(MB + 8 * s, 1);
    }
    __syncthreads();

    if (tid == 0) {
        #pragma unroll
        for (int s = 0; s < STAGES; ++s) {
            mbar_expect_tx(MB + 8 * s, TXB);
            tma_2d(sb + SM_A32 + s * A32_BYTES, tma_a, (c0 + s) * KC, m0g, MB + 8 * s);
            wait_flag(&g_flag[(c0 + s) >> 1]);
            bulk_cp(sb + SM_B + s * BCHUNK_B, g_zh + (size_t)(c0 + s) * BCHUNK_H,
                    BCHUNK_B, MB + 8 * s);
        }
    }

    uint32_t aoff[4];
    #pragma unroll
    for (int mi = 0; mi < 4; ++mi)
        aoff[mi] = (uint32_t)((m0w + mi * 16 + (lane & 15)) * A16_ROWB + (lane >> 4) * 16);
    const int bg = lane >> 3;
    const uint32_t boff =
        (uint32_t)((n0w + ((bg >> 1) & 1) * 8 + (lane & 7)) * BROW_B + (bg & 1) * 16);

    float acc[4][4][4];
    #pragma unroll
    for (int i = 0; i < 4; i++)
        #pragma unroll
        for (int j = 0; j < 4; j++)
            #pragma unroll
            for (int k = 0; k < 4; k++) acc[i][j][k] = 0.f;

    // prologue: convert chunk 0 into ping[0]
    mbar_wait(MB + 8 * 0, 0);
    convert_chunk(smem + SM_A32 + 0 * A32_BYTES, smem + SM_A16 + 0 * A16_BYTES, tid);
    __syncthreads();

    int s = 0, ph = 0;
    #pragma unroll 1
    for (int it = 0; it < SEG_CHUNKS; ++it) {
        const uint32_t bst  = sb + SM_B + s * BCHUNK_B;
        const uint32_t a16b = sb + SM_A16 + (uint32_t)(it & 1) * A16_BYTES;

        // --- pre-barrier: B fragments (both ks) ---
        uint32_t bfr[2][2][4];
        #pragma unroll
        for (int nt2 = 0; nt2 < 2; ++nt2)
            #pragma unroll
            for (int ks = 0; ks < 2; ++ks)
                ldm_x4(bfr[nt2][ks], bst + boff + nt2 * 16 * BROW_B + ks * 32);

        // --- pre-barrier: A fragments ks=0 + MMA ks=0 ---
        {
            uint32_t afr0[4][4];
            #pragma unroll
            for (int mi = 0; mi < 4; ++mi)
                ldm_x4(afr0[mi], a16b + aoff[mi]);
            #pragma unroll
            for (int mi = 0; mi < 4; ++mi)
                #pragma unroll
                for (int nt = 0; nt < 4; ++nt)
                    mma16816(acc[mi][nt], afr0[mi], &bfr[nt >> 1][0][(nt & 1) * 2]);
        }

        // --- pre-barrier: A fragments ks=1 ---
        uint32_t afr1[4][4];
        #pragma unroll
        for (int mi = 0; mi < 4; ++mi)
            ldm_x4(afr1[mi], a16b + aoff[mi] + 32);

        // --- pre-barrier: convert chunk it+1 into the other ping buffer ---
        if (it + 1 < SEG_CHUNKS) {
            int sn  = (s + 1 == STAGES) ? 0 : s + 1;
            int phn = (s + 1 == STAGES) ? (ph ^ 1) : ph;
            mbar_wait(MB + 8 * sn, phn);
            convert_chunk(smem + SM_A32 + sn * A32_BYTES,
                          smem + SM_A16 + ((it + 1) & 1) * A16_BYTES, tid);
        }

        __syncthreads();

        // --- post-barrier: refill stage s ---
        if (tid == 0) {
            int nxt = it + STAGES;
            if (nxt < SEG_CHUNKS) {
                mbar_expect_tx(MB + 8 * s, TXB);
                tma_2d(sb + SM_A32 + s * A32_BYTES, tma_a, (c0 + nxt) * KC, m0g, MB + 8 * s);
                wait_flag(&g_flag[(c0 + nxt) >> 1]);
                bulk_cp(sb + SM_B + s * BCHUNK_B, g_zh + (size_t)(c0 + nxt) * BCHUNK_H,
                        BCHUNK_B, MB + 8 * s);
            }
        }

        // --- post-barrier: MMA ks=1 (overlaps next iter's loads) ---
        #pragma unroll
        for (int mi = 0; mi < 4; ++mi)
            #pragma unroll
            for (int nt = 0; nt < 4; ++nt)
                mma16816(acc[mi][nt], afr1[mi], &bfr[nt >> 1][1][(nt & 1) * 2]);

        if (++s == STAGES) { s = 0; ph ^= 1; }
    }

    // --- epilogue: store raw fp32 partials ---
    float* part = g_part + (size_t)seg * NNODES * DIM;
    #pragma unroll
    for (int mi = 0; mi < 4; ++mi) {
        int r = m0w + mi * 16 + (lane >> 2);
        #pragma unroll
        for (int nt = 0; nt < 4; ++nt) {
            int c = n0w + nt * 8 + 2 * (lane & 3);
            size_t i0 = (size_t)(m0g + r) * DIM + c;
            const float* a = acc[mi][nt];
            *reinterpret_cast<float2*>(part + i0)           = make_float2(a[0], a[1]);
            *reinterpret_cast<float2*>(part + i0 + 8 * DIM) = make_float2(a[2], a[3]);
        }
    }
}

// ============================================================================
// Fused kernel: CTAs 0..255 prep, 256..767 gemm (overlap via ready flags).
// ============================================================================
__global__ void __launch_bounds__(256, 2) fused_kernel(
    const __grid_constant__ CUtensorMap tma_a,
    const float* __restrict__ x,
    const float* __restrict__ W,
    const float* __restrict__ b) {
    extern __shared__ char smem[];
    const uint32_t sb = smem_u32(smem);
    if (blockIdx.x < PREP_CTAS) {
        prep_body(smem, sb, blockIdx.x, x, W, b);
    } else {
        gemm_body(smem, sb, blockIdx.x - PREP_CTAS, &tma_a);
    }
}

// ============================================================================
// Kernel 2 (combine): out = ReLU(p0+p1+p2+p3+u); block 0 also clears flags
// for the next graph replay (safe: runs after all producers/consumers).
// ============================================================================
__global__ __launch_bounds__(256) void combine_kernel(float* __restrict__ out) {
    if (blockIdx.x == 0) g_flag[threadIdx.x] = 0;   // 256 flags, 256 threads
    const size_t i = (size_t)blockIdx.x * 256 + threadIdx.x;
    const size_t stride4 = (size_t)NNODES * DIM / 4;
    const float4* p = reinterpret_cast<const float4*>(g_part);
    const float4* uu = reinterpret_cast<const float4*>(g_u);
    float4 a0 = p[i], a1 = p[i + stride4], a2 = p[i + 2 * stride4], a3 = p[i + 3 * stride4];
    float4 u = uu[i];
    float4 o;
    o.x = fmaxf((a0.x + a1.x) + (a2.x + a3.x) + u.x, 0.f);
    o.y = fmaxf((a0.y + a1.y) + (a2.y + a3.y) + u.y, 0.f);
    o.z = fmaxf((a0.z + a1.z) + (a2.z + a3.z) + u.z, 0.f);
    o.w = fmaxf((a0.w + a1.w) + (a2.w + a3.w) + u.w, 0.f);
    reinterpret_cast<float4*>(out)[i] = o;
}

// ============================================================================
// Host launch
// ============================================================================
typedef CUresult (*EncodeFn)(CUtensorMap*, CUtensorMapDataType, cuuint32_t, void*,
                             const cuuint64_t*, const cuuint64_t*, const cuuint32_t*,
                             const cuuint32_t*, CUtensorMapInterleave, CUtensorMapSwizzle,
                             CUtensorMapL2promotion, CUtensorMapFloatOOBfill);

extern "C" void kernel_launch(void* const* d_in, const int* in_sizes, int n_in,
                              void* d_out, int out_size) {
    const float *x = nullptr, *adj = nullptr, *W = nullptr, *b = nullptr;
    for (int i = 0; i < n_in; ++i) {
        switch (in_sizes[i]) {
            case NNODES * DIM: x = (const float*)d_in[i]; break;
            case 32768:        W = (const float*)d_in[i]; break;
            case 128:          b = (const float*)d_in[i]; break;
            default:           adj = (const float*)d_in[i]; break;
        }
    }
    float* out = (float*)d_out;

    void* fn = nullptr;
    cudaDriverEntryPointQueryResult qr;
#if CUDART_VERSION >= 12050
    cudaGetDriverEntryPointByVersion("cuTensorMapEncodeTiled", &fn, 12000,
                                     cudaEnableDefault, &qr);
#else
    cudaGetDriverEntryPoint("cuTensorMapEncodeTiled", &fn, cudaEnableDefault, &qr);
#endif
    if (!fn) return;
    EncodeFn encode = (EncodeFn)fn;

    CUtensorMap mapA;
    {
        cuuint64_t dims[2]   = {NNODES, NNODES};
        cuuint64_t stride[1] = {NNODES * 4ull};
        cuuint32_t box[2]    = {KC, MTILE};        // 128B x 128 rows, SW128
        cuuint32_t es[2]     = {1, 1};
        encode(&mapA, CU_TENSOR_MAP_DATA_TYPE_FLOAT32, 2, (void*)adj, dims, stride, box, es,
               CU_TENSOR_MAP_INTERLEAVE_NONE, CU_TENSOR_MAP_SWIZZLE_128B,
               CU_TENSOR_MAP_L2_PROMOTION_L2_128B, CU_TENSOR_MAP_FLOAT_OOB_FILL_NONE);
    }

    cudaFuncSetAttribute(fused_kernel, cudaFuncAttributeMaxDynamicSharedMemorySize, FUSED_SMEM);

    fused_kernel<<<PREP_CTAS + GEMM_CTAS, 256, FUSED_SMEM>>>(mapA, x, W, b);
    combine_kernel<<<(NNODES * DIM / 4) / 256, 256>>>(out);
}

// round 15
// speedup vs baseline: 1.1850x; 1.1850x over previous
#include <cuda_runtime.h>
#include <cuda.h>
#include <cuda_fp16.h>
#include <cstdint>

// ---------------- problem constants ----------------
#define NNODES 16384
#define DIM    128
#define KC     32                          // K per chunk
#define CHUNKS (NNODES / KC)               // 512 chunks per m-tile (full K)
#define MTILE  128
#define NMTILES (NNODES / MTILE)           // 128
#define NSLOTS 4                           // max CTAs touching one m-tile
#define TOTCH  (NMTILES * CHUNKS)          // 65536 linearized work units
#define WCTAS  296                         // one wave: 148 SMs x 2 CTAs
#define LEN_A  222                         // first 120 CTAs
#define LEN_B  221                         // remaining 176 CTAs
#define SPLIT_G (120 * LEN_A)              // 26640
#define STAGES 3

// B (zh) padded chunk layout: [chunk][o:128][40 halves] (32 data + 8 pad, 80B rows)
#define BROW_H   40
#define BROW_B   80
#define BCHUNK_H (DIM * BROW_H)            // 5120 halves = 10240 B
#define BCHUNK_B (BCHUNK_H * 2)

#define A32_BYTES (MTILE * KC * 4)         // 16384 B per stage (SW128 swizzled fp32)
#define A16_ROWB  80                       // padded fp16 A row stride
#define A16_BYTES (MTILE * A16_ROWB)       // 10240 B per ping buffer
#define TXB (A32_BYTES + BCHUNK_B)         // 26624

// smem layout (gemm kernel) — no static __shared__ anywhere (a static alloc
// shifts the dynamic base and breaks TMA's 128B alignment: R10/R12 crashes)
#define SM_MBAR 0
#define SM_A32  1024
#define SM_B    (1024 + STAGES * A32_BYTES)              // 50176
#define SM_A16  (SM_B + STAGES * BCHUNK_B)               // 80896
#define GEMM_SMEM (SM_A16 + 2 * A16_BYTES)               // 101376 -> 2 CTAs/SM

// scratch (__device__ globals; 256B-aligned). Unused g_part slots are never
// written and stay zero from module init (combine always sums 4 slots).
__device__ __align__(256) __half g_zh[CHUNKS * BCHUNK_H];       // 5 MB
__device__ __align__(256) float  g_u [NNODES * DIM];            // 8 MB
__device__ __align__(256) float  g_part[NSLOTS * NNODES * DIM]; // 32 MB

// ---------------- PTX helpers (compute_103-baseline only) ----------------
__device__ __forceinline__ uint32_t smem_u32(const void* p) {
    uint32_t a;
    asm("{ .reg .u64 t; cvta.to.shared.u64 t, %1; cvt.u32.u64 %0, t; }" : "=r"(a) : "l"(p));
    return a;
}
__device__ __forceinline__ void mbar_init(uint32_t mbar, uint32_t cnt) {
    asm volatile("mbarrier.init.shared.b64 [%0], %1;" :: "r"(mbar), "r"(cnt) : "memory");
}
__device__ __forceinline__ void mbar_expect_tx(uint32_t mbar, uint32_t bytes) {
    asm volatile("mbarrier.arrive.expect_tx.shared.b64 _, [%0], %1;" :: "r"(mbar), "r"(bytes) : "memory");
}
__device__ __forceinline__ void mbar_wait(uint32_t mbar, uint32_t parity) {
    asm volatile(
        "{\n\t.reg .pred P;\n\t"
        "W_%=:\n\t"
        "mbarrier.try_wait.parity.shared.b64 P, [%0], %1, 0x989680;\n\t"
        "@P bra D_%=;\n\t"
        "bra W_%=;\n\t"
        "D_%=:\n\t}"
        :: "r"(mbar), "r"(parity) : "memory");
}
__device__ __forceinline__ void tma_2d(uint32_t dst, const CUtensorMap* map,
                                       int cx, int cy, uint32_t mbar) {
    asm volatile(
        "cp.async.bulk.tensor.2d.shared::cta.global.tile.mbarrier::complete_tx::bytes "
        "[%0], [%1, {%2, %3}], [%4];"
        :: "r"(dst), "l"(map), "r"(cx), "r"(cy), "r"(mbar) : "memory");
}
__device__ __forceinline__ void bulk_cp(uint32_t dst, const void* src, uint32_t bytes, uint32_t mbar) {
    asm volatile(
        "cp.async.bulk.shared::cta.global.mbarrier::complete_tx::bytes [%0], [%1], %2, [%3];"
        :: "r"(dst), "l"(src), "r"(bytes), "r"(mbar) : "memory");
}
__device__ __forceinline__ void ldm_x4(uint32_t* r, uint32_t addr) {
    asm volatile("ldmatrix.sync.aligned.m8n8.x4.shared.b16 {%0,%1,%2,%3}, [%4];"
        : "=r"(r[0]), "=r"(r[1]), "=r"(r[2]), "=r"(r[3]) : "r"(addr));
}
__device__ __forceinline__ void mma16816(float* c, const uint32_t* a, const uint32_t* b) {
    asm volatile("mma.sync.aligned.m16n8k16.row.col.f32.f16.f16.f32 "
        "{%0,%1,%2,%3}, {%4,%5,%6,%7}, {%8,%9}, {%0,%1,%2,%3};"
        : "+f"(c[0]), "+f"(c[1]), "+f"(c[2]), "+f"(c[3])
        : "r"(a[0]), "r"(a[1]), "r"(a[2]), "r"(a[3]), "r"(b[0]), "r"(b[1]));
}

// fp32 SW128 stage (128 rows x 128B) -> padded fp16 ping buffer (256 threads)
__device__ __forceinline__ void convert_chunk(const char* a32, char* a16, int tid) {
    const int crow = tid >> 1, chalf = tid & 1;
    const uint32_t rsw = (uint32_t)(crow & 7) << 4;
    char* dst = a16 + crow * A16_ROWB + chalf * 32;
    #pragma unroll
    for (int jp = 0; jp < 2; ++jp) {
        uint32_t b0 = (uint32_t)(crow * 128 + chalf * 64 + jp * 32);
        float4 v0 = *reinterpret_cast<const float4*>(a32 + (b0 ^ rsw));
        float4 v1 = *reinterpret_cast<const float4*>(a32 + ((b0 + 16) ^ rsw));
        __half2 h0 = __floats2half2_rn(v0.x, v0.y);
        __half2 h1 = __floats2half2_rn(v0.z, v0.w);
        __half2 h2 = __floats2half2_rn(v1.x, v1.y);
        __half2 h3 = __floats2half2_rn(v1.z, v1.w);
        uint4 pk;
        pk.x = *reinterpret_cast<uint32_t*>(&h0);
        pk.y = *reinterpret_cast<uint32_t*>(&h1);
        pk.z = *reinterpret_cast<uint32_t*>(&h2);
        pk.w = *reinterpret_cast<uint32_t*>(&h3);
        *reinterpret_cast<uint4*>(dst + jp * 16) = pk;
    }
}

// linear chunk index -> owning CTA (static schedule inverse)
__device__ __forceinline__ int cta_of(int g) {
    return (g < SPLIT_G) ? (g / LEN_A) : (120 + (g - SPLIT_G) / LEN_B);
}

// flush accumulators to a partial slot, then zero them
__device__ __forceinline__ void flush_acc(float acc[4][4][4], int slot, int mt,
                                          int m0w, int n0w, int lane) {
    float* part = g_part + (size_t)slot * NNODES * DIM;
    const int m0g = mt * MTILE;
    #pragma unroll
    for (int mi = 0; mi < 4; ++mi) {
        int r = m0w + mi * 16 + (lane >> 2);
        #pragma unroll
        for (int nt = 0; nt < 4; ++nt) {
            int c = n0w + nt * 8 + 2 * (lane & 3);
            size_t i0 = (size_t)(m0g + r) * DIM + c;
            float* a = acc[mi][nt];
            *reinterpret_cast<float2*>(part + i0)           = make_float2(a[0], a[1]);
            *reinterpret_cast<float2*>(part + i0 + 8 * DIM) = make_float2(a[2], a[3]);
            a[0] = a[1] = a[2] = a[3] = 0.f;
        }
    }
}

// ============================================================================
// Kernel 1 (prep, tensor-core): 256 CTAs x 256 threads, 64 nodes/CTA.
//   (proven — measured 12.4us)
// ============================================================================
#define PT_ROWB 272
#define PT_XH   1024
#define PT_WH   (PT_XH + 64 * PT_ROWB)     // 18432
#define PT_ZS   (PT_WH + 256 * PT_ROWB)    // 88064
#define ZS_STRH 72
#define PREP_SMEM (PT_ZS + 128 * ZS_STRH * 2)   // 106496

__global__ void __launch_bounds__(256, 2) prep_kernel(const float* __restrict__ x,
                                                      const float* __restrict__ W,
                                                      const float* __restrict__ b) {
    extern __shared__ char smem[];
    const uint32_t sb = smem_u32(smem);
    const int tid  = threadIdx.x;
    const int lane = tid & 31;
    const int w    = tid >> 5;
    const int node0 = blockIdx.x * 64;

    #pragma unroll
    for (int i = 0; i < 8; ++i) {
        int idx = tid + i * 256;
        int row = idx >> 5, c4 = idx & 31;
        float4 v = reinterpret_cast<const float4*>(x + (size_t)(node0 + row) * DIM)[c4];
        __half2 h0 = __floats2half2_rn(v.x, v.y);
        __half2 h1 = __floats2half2_rn(v.z, v.w);
        uint2 pk;
        pk.x = *reinterpret_cast<uint32_t*>(&h0);
        pk.y = *reinterpret_cast<uint32_t*>(&h1);
        *reinterpret_cast<uint2*>(smem + PT_XH + row * PT_ROWB + c4 * 8) = pk;
    }
    #pragma unroll
    for (int i = 0; i < 32; ++i) {
        int idx = tid + i * 256;
        int j = idx >> 5, c4 = idx & 31;
        const float* src = (j < DIM) ? (W + j * 256 + DIM) : (W + (j - DIM) * 256);
        float4 v = reinterpret_cast<const float4*>(src)[c4];
        __half2 h0 = __floats2half2_rn(v.x, v.y);
        __half2 h1 = __floats2half2_rn(v.z, v.w);
        uint2 pk;
        pk.x = *reinterpret_cast<uint32_t*>(&h0);
        pk.y = *reinterpret_cast<uint32_t*>(&h1);
        *reinterpret_cast<uint2*>(smem + PT_WH + j * PT_ROWB + c4 * 8) = pk;
    }
    __syncthreads();

    const int m0w = (w >> 2) * 32;
    const int n0w = (w & 3) * 64;
    uint32_t aoff[2];
    #pragma unroll
    for (int mi = 0; mi < 2; ++mi)
        aoff[mi] = (uint32_t)(PT_XH + (m0w + mi * 16 + (lane & 15)) * PT_ROWB + (lane >> 4) * 16);
    const int bg = lane >> 3;
    const uint32_t boff =
        (uint32_t)(PT_WH + (n0w + ((bg >> 1) & 1) * 8 + (lane & 7)) * PT_ROWB + (bg & 1) * 16);

    float acc[2][8][4];
    #pragma unroll
    for (int i = 0; i < 2; i++)
        #pragma unroll
        for (int j = 0; j < 8; j++)
            #pragma unroll
            for (int k = 0; k < 4; k++) acc[i][j][k] = 0.f;

    #pragma unroll
    for (int ks = 0; ks < 8; ++ks) {
        uint32_t afr[2][4];
        #pragma unroll
        for (int mi = 0; mi < 2; ++mi)
            ldm_x4(afr[mi], sb + aoff[mi] + ks * 32);
        uint32_t bfr[4][4];
        #pragma unroll
        for (int nt2 = 0; nt2 < 4; ++nt2)
            ldm_x4(bfr[nt2], sb + boff + nt2 * 16 * PT_ROWB + ks * 32);
        #pragma unroll
        for (int mi = 0; mi < 2; ++mi)
            #pragma unroll
            for (int nt = 0; nt < 8; ++nt)
                mma16816(acc[mi][nt], afr[mi], &bfr[nt >> 1][(nt & 1) * 2]);
    }

    __half* zs = reinterpret_cast<__half*>(smem + PT_ZS);
    if (n0w < 128) {
        #pragma unroll
        for (int mi = 0; mi < 2; ++mi) {
            int r = m0w + mi * 16 + (lane >> 2);
            #pragma unroll
            for (int nt = 0; nt < 8; ++nt) {
                int n = n0w + nt * 8 + 2 * (lane & 3);
                const float* a = acc[mi][nt];
                zs[n * ZS_STRH + r]           = __float2half_rn(a[0]);
                zs[(n + 1) * ZS_STRH + r]     = __float2half_rn(a[1]);
                zs[n * ZS_STRH + r + 8]       = __float2half_rn(a[2]);
                zs[(n + 1) * ZS_STRH + r + 8] = __float2half_rn(a[3]);
            }
        }
    } else {
        #pragma unroll
        for (int mi = 0; mi < 2; ++mi) {
            int r = m0w + mi * 16 + (lane >> 2);
            #pragma unroll
            for (int nt = 0; nt < 8; ++nt) {
                int o = n0w - 128 + nt * 8 + 2 * (lane & 3);
                float2 bo = *reinterpret_cast<const float2*>(b + o);
                const float* a = acc[mi][nt];
                *reinterpret_cast<float2*>(g_u + (size_t)(node0 + r) * DIM + o) =
                    make_float2(a[0] + bo.x, a[1] + bo.y);
                *reinterpret_cast<float2*>(g_u + (size_t)(node0 + r + 8) * DIM + o) =
                    make_float2(a[2] + bo.x, a[3] + bo.y);
            }
        }
    }
    __syncthreads();

    {
        int o = tid >> 1, q = tid & 1;
        const uint4* src = reinterpret_cast<const uint4*>(smem + PT_ZS + o * (ZS_STRH * 2) + q * 64);
        uint4* dst = reinterpret_cast<uint4*>(g_zh + (size_t)(blockIdx.x * 2 + q) * BCHUNK_H + o * BROW_H);
        #pragma unroll
        for (int i = 0; i < 4; i++) dst[i] = src[i];
    }
}

// ============================================================================
// Kernel 2 (main): 296 persistent CTAs x 256 threads, ONE wave (2 CTAs/SM).
//   Each CTA streams a contiguous 221/222-chunk range of the linearized
//   (mtile x chunk) space; crosses at most one mtile boundary (accumulator
//   flush to a partial slot). Proven R9 pipeline: staged fp32->fp16 convert,
//   ldmatrix fragments, warp grid 2(M) x 4(N), ks=0 MMA pre-barrier.
// ============================================================================
__global__ void __launch_bounds__(256, 2) gemm_kernel(
    const __grid_constant__ CUtensorMap tma_a) {
    extern __shared__ char smem[];
    const uint32_t sb = smem_u32(smem);
    const uint32_t MB = sb + SM_MBAR;

    const int tid  = threadIdx.x;
    const int lane = tid & 31;
    const int w    = tid >> 5;
    const int bx   = blockIdx.x;
    const int g0   = (bx < 120) ? LEN_A * bx : SPLIT_G + LEN_B * (bx - 120);
    const int len  = (bx < 120) ? LEN_A : LEN_B;
    const int mtA    = g0 >> 9;
    const int mtLast = (g0 + len - 1) >> 9;
    const int itB    = (mtA == mtLast) ? len : ((mtLast << 9) - g0); // first iter of mtLast
    const int slotA  = bx - cta_of(mtA << 9);      // slot of mtLast (if crossed) is 0
    const int m0w  = (w >> 2) * 64;     // warp tile 64x32
    const int n0w  = (w & 3) * 32;

    if (tid == 0) {
        #pragma unroll
        for (int s = 0; s < STAGES; ++s) mbar_init(MB + 8 * s, 1);
    }
    __syncthreads();

    if (tid == 0) {
        #pragma unroll
        for (int s = 0; s < STAGES; ++s) {
            int gg = g0 + s;
            mbar_expect_tx(MB + 8 * s, TXB);
            tma_2d(sb + SM_A32 + s * A32_BYTES, &tma_a, (gg & 511) * KC, (gg >> 9) * MTILE,
                   MB + 8 * s);
            bulk_cp(sb + SM_B + s * BCHUNK_B, g_zh + (size_t)(gg & 511) * BCHUNK_H,
                    BCHUNK_B, MB + 8 * s);
        }
    }

    uint32_t aoff[4];
    #pragma unroll
    for (int mi = 0; mi < 4; ++mi)
        aoff[mi] = (uint32_t)((m0w + mi * 16 + (lane & 15)) * A16_ROWB + (lane >> 4) * 16);
    const int bg = lane >> 3;
    const uint32_t boff =
        (uint32_t)((n0w + ((bg >> 1) & 1) * 8 + (lane & 7)) * BROW_B + (bg & 1) * 16);

    float acc[4][4][4];
    #pragma unroll
    for (int i = 0; i < 4; i++)
        #pragma unroll
        for (int j = 0; j < 4; j++)
            #pragma unroll
            for (int k = 0; k < 4; k++) acc[i][j][k] = 0.f;

    // prologue: convert chunk 0 into ping[0]
    mbar_wait(MB + 8 * 0, 0);
    convert_chunk(smem + SM_A32 + 0 * A32_BYTES, smem + SM_A16 + 0 * A16_BYTES, tid);
    __syncthreads();

    int s = 0, ph = 0;
    #pragma unroll 1
    for (int it = 0; it < len; ++it) {
        // mtile boundary: flush mtA's accumulators before any MMA of mtLast
        if (it == itB)
            flush_acc(acc, slotA, mtA, m0w, n0w, lane);

        const uint32_t bst  = sb + SM_B + s * BCHUNK_B;
        const uint32_t a16b = sb + SM_A16 + (uint32_t)(it & 1) * A16_BYTES;

        // --- pre-barrier: B fragments (both ks) ---
        uint32_t bfr[2][2][4];
        #pragma unroll
        for (int nt2 = 0; nt2 < 2; ++nt2)
            #pragma unroll
            for (int ks = 0; ks < 2; ++ks)
                ldm_x4(bfr[nt2][ks], bst + boff + nt2 * 16 * BROW_B + ks * 32);

        // --- pre-barrier: A fragments ks=0 + MMA ks=0 (frees regs early) ---
        {
            uint32_t afr0[4][4];
            #pragma unroll
            for (int mi = 0; mi < 4; ++mi)
                ldm_x4(afr0[mi], a16b + aoff[mi]);
            #pragma unroll
            for (int mi = 0; mi < 4; ++mi)
                #pragma unroll
                for (int nt = 0; nt < 4; ++nt)
                    mma16816(acc[mi][nt], afr0[mi], &bfr[nt >> 1][0][(nt & 1) * 2]);
        }

        // --- pre-barrier: A fragments ks=1 ---
        uint32_t afr1[4][4];
        #pragma unroll
        for (int mi = 0; mi < 4; ++mi)
            ldm_x4(afr1[mi], a16b + aoff[mi] + 32);

        // --- pre-barrier: convert chunk it+1 into the other ping buffer ---
        if (it + 1 < len) {
            int sn  = (s + 1 == STAGES) ? 0 : s + 1;
            int phn = (s + 1 == STAGES) ? (ph ^ 1) : ph;
            mbar_wait(MB + 8 * sn, phn);
            convert_chunk(smem + SM_A32 + sn * A32_BYTES,
                          smem + SM_A16 + ((it + 1) & 1) * A16_BYTES, tid);
        }

        __syncthreads();

        // --- post-barrier: refill stage s with chunk it+STAGES ---
        if (tid == 0) {
            int nxt = it + STAGES;
            if (nxt < len) {
                int gg = g0 + nxt;
                mbar_expect_tx(MB + 8 * s, TXB);
                tma_2d(sb + SM_A32 + s * A32_BYTES, &tma_a, (gg & 511) * KC, (gg >> 9) * MTILE,
                       MB + 8 * s);
                bulk_cp(sb + SM_B + s * BCHUNK_B, g_zh + (size_t)(gg & 511) * BCHUNK_H,
                        BCHUNK_B, MB + 8 * s);
            }
        }

        // --- post-barrier: MMA ks=1 (overlaps next iter's loads) ---
        #pragma unroll
        for (int mi = 0; mi < 4; ++mi)
            #pragma unroll
            for (int nt = 0; nt < 4; ++nt)
                mma16816(acc[mi][nt], afr1[mi], &bfr[nt >> 1][1][(nt & 1) * 2]);

        if (++s == STAGES) { s = 0; ph ^= 1; }
    }

    // final flush: last mtile's slot is 0 if we crossed a boundary, else slotA
    flush_acc(acc, (mtA == mtLast) ? slotA : 0, mtLast, m0w, n0w, lane);
}

// ============================================================================
// Kernel 3 (combine): out = ReLU(p0+p1+p2+p3+u), elementwise float4.
//   Slots never written by any CTA remain zero from module init.
// ============================================================================
__global__ __launch_bounds__(256) void combine_kernel(float* __restrict__ out) {
    const size_t i = (size_t)blockIdx.x * 256 + threadIdx.x;
    const size_t stride4 = (size_t)NNODES * DIM / 4;
    const float4* p = reinterpret_cast<const float4*>(g_part);
    const float4* uu = reinterpret_cast<const float4*>(g_u);
    float4 a0 = p[i], a1 = p[i + stride4], a2 = p[i + 2 * stride4], a3 = p[i + 3 * stride4];
    float4 u = uu[i];
    float4 o;
    o.x = fmaxf((a0.x + a1.x) + (a2.x + a3.x) + u.x, 0.f);
    o.y = fmaxf((a0.y + a1.y) + (a2.y + a3.y) + u.y, 0.f);
    o.z = fmaxf((a0.z + a1.z) + (a2.z + a3.z) + u.z, 0.f);
    o.w = fmaxf((a0.w + a1.w) + (a2.w + a3.w) + u.w, 0.f);
    reinterpret_cast<float4*>(out)[i] = o;
}

// ============================================================================
// Host launch
// ============================================================================
typedef CUresult (*EncodeFn)(CUtensorMap*, CUtensorMapDataType, cuuint32_t, void*,
                             const cuuint64_t*, const cuuint64_t*, const cuuint32_t*,
                             const cuuint32_t*, CUtensorMapInterleave, CUtensorMapSwizzle,
                             CUtensorMapL2promotion, CUtensorMapFloatOOBfill);

extern "C" void kernel_launch(void* const* d_in, const int* in_sizes, int n_in,
                              void* d_out, int out_size) {
    const float *x = nullptr, *adj = nullptr, *W = nullptr, *b = nullptr;
    for (int i = 0; i < n_in; ++i) {
        switch (in_sizes[i]) {
            case NNODES * DIM: x = (const float*)d_in[i]; break;
            case 32768:        W = (const float*)d_in[i]; break;
            case 128:          b = (const float*)d_in[i]; break;
            default:           adj = (const float*)d_in[i]; break;
        }
    }
    float* out = (float*)d_out;

    void* fn = nullptr;
    cudaDriverEntryPointQueryResult qr;
#if CUDART_VERSION >= 12050
    cudaGetDriverEntryPointByVersion("cuTensorMapEncodeTiled", &fn, 12000,
                                     cudaEnableDefault, &qr);
#else
    cudaGetDriverEntryPoint("cuTensorMapEncodeTiled", &fn, cudaEnableDefault, &qr);
#endif
    if (!fn) return;
    EncodeFn encode = (EncodeFn)fn;

    CUtensorMap mapA;
    {
        cuuint64_t dims[2]   = {NNODES, NNODES};
        cuuint64_t stride[1] = {NNODES * 4ull};
        cuuint32_t box[2]    = {KC, MTILE};        // 128B x 128 rows, SW128
        cuuint32_t es[2]     = {1, 1};
        encode(&mapA, CU_TENSOR_MAP_DATA_TYPE_FLOAT32, 2, (void*)adj, dims, stride, box, es,
               CU_TENSOR_MAP_INTERLEAVE_NONE, CU_TENSOR_MAP_SWIZZLE_128B,
               CU_TENSOR_MAP_L2_PROMOTION_L2_128B, CU_TENSOR_MAP_FLOAT_OOB_FILL_NONE);
    }

    cudaFuncSetAttribute(prep_kernel, cudaFuncAttributeMaxDynamicSharedMemorySize, PREP_SMEM);
    cudaFuncSetAttribute(gemm_kernel, cudaFuncAttributeMaxDynamicSharedMemorySize, GEMM_SMEM);

    prep_kernel<<<NNODES / 64, 256, PREP_SMEM>>>(x, W, b);
    gemm_kernel<<<WCTAS, 256, GEMM_SMEM>>>(mapA);
    combine_kernel<<<(NNODES * DIM / 4) / 256, 256>>>(out);
}